// round 15
// baseline (speedup 1.0000x reference)
#include <cuda_runtime.h>
#include <cuda_fp16.h>
#include <cstdint>

#define N_NODES 50000
#define M_PAD   50048            // 391 * 128
#define N_EDGES 800000
#define FEAT    256
#define N_RELS  8
#define KA      2048             // A width (agg blocks only; x comes from g_xh)
#define KTOT    2304             // GEMM K = KA + FEAT
#define N_BUCK  (N_NODES * N_RELS)
#define SQRT_HALF 0.70710678118654752f

// ---------------- scratch ----------------------------------------------------
__device__ __half g_A[(size_t)M_PAD * KA];            // [aggx_0..7], fp16
__device__ __half g_xh[(size_t)M_PAD * FEAT];         // fp16 x
__device__ __half g_wt2[(size_t)FEAT * KTOT];         // [n][k] = W^T * sqrt(0.5)
__device__ int      g_counts[N_BUCK];
__device__ int      g_offsets[N_BUCK + 1];
__device__ int      g_cursor[N_BUCK];
__device__ int      g_blocksum[400];
__device__ int      g_blockpre[400];
__device__ unsigned g_sorted[N_EDGES];
__device__ unsigned g_tile_ctr;

#define SCAN_NB ((N_BUCK + 1023) / 1024)   // 391

// ---------------- sort pipeline: key = dst*8 + rel ---------------------------
__global__ void k_zero_counts() {
    int i = blockIdx.x * blockDim.x + threadIdx.x;
    if (i < N_BUCK) g_counts[i] = 0;
    if (i == 0) g_tile_ctr = 0;
}

__global__ void k_hist(const int* __restrict__ edge_index,
                       const int* __restrict__ edge_type) {
    int e = blockIdx.x * blockDim.x + threadIdx.x;
    if (e < N_EDGES) {
        int d = edge_index[N_EDGES + e];
        int r = edge_type[e];
        if (d >= 0 && d < N_NODES)
            atomicAdd(&g_counts[d * N_RELS + r], 1);
    }
}

__global__ void k_scan1() {
    __shared__ int s[1024];
    int idx = blockIdx.x * 1024 + threadIdx.x;
    int v = (idx < N_BUCK) ? g_counts[idx] : 0;
    s[threadIdx.x] = v;
    __syncthreads();
    for (int off = 512; off > 0; off >>= 1) {
        if (threadIdx.x < off) s[threadIdx.x] += s[threadIdx.x + off];
        __syncthreads();
    }
    if (threadIdx.x == 0) g_blocksum[blockIdx.x] = s[0];
}

__global__ void k_scan2() {
    __shared__ int s[512];
    int t = threadIdx.x;
    int v = (t < SCAN_NB) ? g_blocksum[t] : 0;
    s[t] = v;
    __syncthreads();
    int val = v;
    for (int off = 1; off < 512; off <<= 1) {
        int u = (t >= off) ? s[t - off] : 0;
        __syncthreads();
        val += u;
        s[t] = val;
        __syncthreads();
    }
    if (t < SCAN_NB) g_blockpre[t] = val - v;
    if (t == 0) g_offsets[N_BUCK] = N_EDGES;
}

__global__ void k_scan3() {
    __shared__ int s[1024];
    int idx = blockIdx.x * 1024 + threadIdx.x;
    int t = threadIdx.x;
    int v = (idx < N_BUCK) ? g_counts[idx] : 0;
    s[t] = v;
    __syncthreads();
    int val = v;
    for (int off = 1; off < 1024; off <<= 1) {
        int u = (t >= off) ? s[t - off] : 0;
        __syncthreads();
        val += u;
        s[t] = val;
        __syncthreads();
    }
    if (idx < N_BUCK) {
        int o = g_blockpre[blockIdx.x] + val - v;
        g_offsets[idx] = o;
        g_cursor[idx]  = o;
    }
}

__global__ void k_scatter(const int* __restrict__ edge_index,
                          const int* __restrict__ edge_type) {
    int e = blockIdx.x * blockDim.x + threadIdx.x;
    if (e < N_EDGES) {
        int srcv = edge_index[e];
        int d    = edge_index[N_EDGES + e];
        int r    = edge_type[e];
        if (d >= 0 && d < N_NODES) {
            int pos = atomicAdd(&g_cursor[d * N_RELS + r], 1);
            g_sorted[pos] = (unsigned)srcv;
        }
    }
}

// ---------------- converts ---------------------------------------------------
__global__ void k_convert_x(const float* __restrict__ x) {
    int i = blockIdx.x * blockDim.x + threadIdx.x;
    const int total = N_NODES * FEAT / 2;
    if (i < total) {
        float2 v = *((const float2*)x + i);
        *((__half2*)g_xh + i) = __floats2half2_rn(v.x, v.y);
    }
}

__global__ void k_convert_w(const float* __restrict__ W, const float* __restrict__ LW) {
    int r = blockIdx.z;
    const float* src = (r < N_RELS) ? (W + (size_t)r * FEAT * FEAT) : LW;
    int k0 = blockIdx.x * 32, n0 = blockIdx.y * 32;
    __shared__ float t[32][33];
    for (int i = threadIdx.y; i < 32; i += 8)
        t[i][threadIdx.x] = src[(size_t)(k0 + i) * FEAT + n0 + threadIdx.x];
    __syncthreads();
    for (int i = threadIdx.y; i < 32; i += 8)
        g_wt2[(size_t)(n0 + i) * KTOT + r * FEAT + k0 + threadIdx.x] =
            __float2half(t[threadIdx.x][i] * SQRT_HALF);
}

// ---------------- edge aggregation: 1 warp per (dst,rel) bucket --------------
// 2-stage software prefetch: next row load in flight while accumulating current.
__global__ __launch_bounds__(256) void k_agg_gather() {
    int p = blockIdx.x * 8 + threadIdx.y;
    if (p >= N_BUCK) return;
    int lane = threadIdx.x;
    int d = p >> 3, r = p & 7;
    int beg = g_offsets[p];
    int end = g_offsets[p + 1];

    float acc[8];
    #pragma unroll
    for (int j = 0; j < 8; j++) acc[j] = 0.f;

    if (beg < end) {
        unsigned s0 = g_sorted[beg];
        uint4 v = __ldg((const uint4*)(g_xh + ((size_t)s0 << 8)) + lane);
        for (int i = beg + 1; i < end; i++) {
            unsigned s1 = g_sorted[i];
            uint4 vn = __ldg((const uint4*)(g_xh + ((size_t)s1 << 8)) + lane);
            float2 f0 = __half22float2(*reinterpret_cast<const __half2*>(&v.x));
            float2 f1 = __half22float2(*reinterpret_cast<const __half2*>(&v.y));
            float2 f2 = __half22float2(*reinterpret_cast<const __half2*>(&v.z));
            float2 f3 = __half22float2(*reinterpret_cast<const __half2*>(&v.w));
            acc[0] += f0.x; acc[1] += f0.y; acc[2] += f1.x; acc[3] += f1.y;
            acc[4] += f2.x; acc[5] += f2.y; acc[6] += f3.x; acc[7] += f3.y;
            v = vn;
        }
        float2 f0 = __half22float2(*reinterpret_cast<const __half2*>(&v.x));
        float2 f1 = __half22float2(*reinterpret_cast<const __half2*>(&v.y));
        float2 f2 = __half22float2(*reinterpret_cast<const __half2*>(&v.z));
        float2 f3 = __half22float2(*reinterpret_cast<const __half2*>(&v.w));
        acc[0] += f0.x; acc[1] += f0.y; acc[2] += f1.x; acc[3] += f1.y;
        acc[4] += f2.x; acc[5] += f2.y; acc[6] += f3.x; acc[7] += f3.y;
    }

    __half2 h0 = __floats2half2_rn(acc[0], acc[1]);
    __half2 h1 = __floats2half2_rn(acc[2], acc[3]);
    __half2 h2 = __floats2half2_rn(acc[4], acc[5]);
    __half2 h3 = __floats2half2_rn(acc[6], acc[7]);
    uint4 o;
    o.x = *reinterpret_cast<unsigned*>(&h0);
    o.y = *reinterpret_cast<unsigned*>(&h1);
    o.z = *reinterpret_cast<unsigned*>(&h2);
    o.w = *reinterpret_cast<unsigned*>(&h3);
    *(uint4*)(g_A + (size_t)d * KA + r * FEAT + lane * 8) = o;
}

// ---------------- fp16 mma GEMM: out = [A|x] @ Wt2^T + bias ------------------
// Persistent 128x128 tiles, 4-stage cp.async, SINGLE sync per iteration
// (loads issued after the sync -> no buffer collision with 4 stages).
#define GBM 128
#define GBN 128
#define GBK 32
#define NSTG 4
#define PITCH 40                       // halfs per smem row (80 B)
#define ASTAGE (GBM * PITCH)           // 5120 halfs
#define BSTAGE (GBN * PITCH)           // 5120 halfs
#define OFF_B  (NSTG * ASTAGE)
#define SMEM_SZ ((NSTG * ASTAGE + NSTG * BSTAGE) * 2)   // 81920 B
#define NTILES ((M_PAD / GBM) * (FEAT / GBN))     // 782
#define GRID_P 296                                 // 148 SMs x 2 CTAs

__device__ __forceinline__ void cp16(void* dst, const void* src) {
    unsigned s = (unsigned)__cvta_generic_to_shared(dst);
    asm volatile("cp.async.cg.shared.global [%0],[%1],16;" :: "r"(s), "l"(src));
}
__device__ __forceinline__ void cp_commit() { asm volatile("cp.async.commit_group;"); }
template<int N> __device__ __forceinline__ void cp_wait() {
    asm volatile("cp.async.wait_group %0;" :: "n"(N));
}
__device__ __forceinline__ void ldm_x4(unsigned r[4], const void* p) {
    unsigned a = (unsigned)__cvta_generic_to_shared(p);
    asm volatile("ldmatrix.sync.aligned.m8n8.x4.shared.b16 {%0,%1,%2,%3},[%4];"
                 : "=r"(r[0]), "=r"(r[1]), "=r"(r[2]), "=r"(r[3]) : "r"(a));
}
__device__ __forceinline__ void mma_f16(float c[4], const unsigned a[4], const unsigned b[2]) {
    asm volatile(
        "mma.sync.aligned.m16n8k16.row.col.f32.f16.f16.f32 "
        "{%0,%1,%2,%3},{%4,%5,%6,%7},{%8,%9},{%0,%1,%2,%3};"
        : "+f"(c[0]), "+f"(c[1]), "+f"(c[2]), "+f"(c[3])
        : "r"(a[0]), "r"(a[1]), "r"(a[2]), "r"(a[3]), "r"(b[0]), "r"(b[1]));
}

__global__ __launch_bounds__(256, 2) void k_gemm_f16(
    const float* __restrict__ h_bias, float* __restrict__ out)
{
    extern __shared__ __half smem[];
    __half* As = smem;            // NSTG stages of GBM x GBK
    __half* Bs = smem + OFF_B;    // NSTG stages of GBN x GBK
    __shared__ unsigned s_tile;

    const int tid  = threadIdx.x;
    const int lane = tid & 31;
    const int warp = tid >> 5;    // 0..7
    const int wm   = warp & 3;    // 4 warps in m: 32 rows each
    const int wn   = warp >> 2;   // 2 warps in n: 64 cols each

    for (;;) {
        if (tid == 0) s_tile = atomicAdd(&g_tile_ctr, 1u);
        __syncthreads();
        unsigned tile = s_tile;
        if (tile >= NTILES) break;

        const int n0 = (int)(tile & 1) * GBN;     // n halves adjacent -> L2 A share
        const int m0 = (int)(tile >> 1) * GBM;

        float c[2][8][4];
        #pragma unroll
        for (int i = 0; i < 2; i++)
            #pragma unroll
            for (int j = 0; j < 8; j++)
                #pragma unroll
                for (int q = 0; q < 4; q++) c[i][j][q] = 0.f;

        auto load_stage = [&](int st, int k0) {
            #pragma unroll
            for (int j = 0; j < 2; j++) {
                int idx = tid + j * 256;
                int row = idx >> 2, seg = idx & 3;   // 128 rows x 4 segs
                const __half* srcA = (k0 < KA)
                    ? g_A  + (size_t)(m0 + row) * KA   + k0          + seg * 8
                    : g_xh + (size_t)(m0 + row) * FEAT + (k0 - KA)  + seg * 8;
                cp16(&As[st * ASTAGE + row * PITCH + seg * 8], srcA);
                cp16(&Bs[st * BSTAGE + row * PITCH + seg * 8],
                     g_wt2 + (size_t)(n0 + row) * KTOT + k0 + seg * 8);
            }
        };

        load_stage(0, 0);       cp_commit();
        load_stage(1, GBK);     cp_commit();
        load_stage(2, 2 * GBK); cp_commit();

        const int NSTAGES = KTOT / GBK;  // 72
        for (int it = 0; it < NSTAGES; it++) {
            int buf = it & 3;
            // wait for this buffer's group; keep up to 2 younger groups in flight
            if (it <= NSTAGES - 3)      cp_wait<2>();
            else if (it == NSTAGES - 2) cp_wait<1>();
            else                        cp_wait<0>();
            __syncthreads();
            // single sync: issue next load only AFTER sync (no buffer collision)
            if (it + 3 < NSTAGES) {
                load_stage((it + 3) & 3, (it + 3) * GBK);
                cp_commit();
            }

            const __half* Ab = &As[buf * ASTAGE];
            const __half* Bb = &Bs[buf * BSTAGE];
            #pragma unroll
            for (int ks = 0; ks < 2; ks++) {
                const int kb = ks * 16;
                unsigned a[2][4];
                #pragma unroll
                for (int mf = 0; mf < 2; mf++) {
                    int mrow = wm * 32 + mf * 16 + (lane & 15);
                    ldm_x4(a[mf], Ab + mrow * PITCH + kb + ((lane >> 4) << 3));
                }
                unsigned b[8][2];
                #pragma unroll
                for (int nb = 0; nb < 4; nb++) {
                    int nrow = wn * 64 + nb * 16 + (lane & 7) + ((lane >> 4) << 3);
                    unsigned t[4];
                    ldm_x4(t, Bb + nrow * PITCH + kb + (((lane >> 3) & 1) << 3));
                    b[2 * nb][0] = t[0]; b[2 * nb][1] = t[1];
                    b[2 * nb + 1][0] = t[2]; b[2 * nb + 1][1] = t[3];
                }
                #pragma unroll
                for (int mf = 0; mf < 2; mf++)
                    #pragma unroll
                    for (int nf = 0; nf < 8; nf++)
                        mma_f16(c[mf][nf], a[mf], b[nf]);
            }
        }
        // ensure all warps done reading smem before next tile's loads
        __syncthreads();

        // epilogue: out = C + bias
        #pragma unroll
        for (int mf = 0; mf < 2; mf++) {
            int row0 = m0 + wm * 32 + mf * 16 + (lane >> 2);
            #pragma unroll
            for (int nf = 0; nf < 8; nf++) {
                int col = n0 + wn * 64 + nf * 8 + (lane & 3) * 2;
                float2 bv = *(const float2*)(h_bias + col);
                if (row0 < N_NODES)
                    *(float2*)(out + ((size_t)row0 << 8) + col) =
                        make_float2(bv.x + c[mf][nf][0], bv.y + c[mf][nf][1]);
                if (row0 + 8 < N_NODES)
                    *(float2*)(out + ((size_t)(row0 + 8) << 8) + col) =
                        make_float2(bv.x + c[mf][nf][2], bv.y + c[mf][nf][3]);
            }
        }
    }
}

// ---------------- launch -----------------------------------------------------
extern "C" void kernel_launch(void* const* d_in, const int* in_sizes, int n_in,
                              void* d_out, int out_size) {
    const int*   edge_index  = (const int*)d_in[0];
    const float* x           = (const float*)d_in[1];
    const int*   edge_type   = (const int*)d_in[2];
    const float* weight      = (const float*)d_in[3];
    const float* h_bias      = (const float*)d_in[4];
    const float* loop_weight = (const float*)d_in[5];
    float* out = (float*)d_out;

    // converts
    k_convert_x<<<(N_NODES * FEAT / 2 + 255) / 256, 256>>>(x);
    {
        dim3 b(32, 8), g(FEAT / 32, FEAT / 32, N_RELS + 1);
        k_convert_w<<<g, b>>>(weight, loop_weight);
    }

    // sort pipeline over (dst, rel) buckets
    k_zero_counts<<<(N_BUCK + 255) / 256, 256>>>();
    k_hist<<<(N_EDGES + 255) / 256, 256>>>(edge_index, edge_type);
    k_scan1<<<SCAN_NB, 1024>>>();
    k_scan2<<<1, 512>>>();
    k_scan3<<<SCAN_NB, 1024>>>();
    k_scatter<<<(N_EDGES + 255) / 256, 256>>>(edge_index, edge_type);

    // edge aggregation into A
    {
        dim3 b(32, 8);
        k_agg_gather<<<(N_BUCK + 7) / 8, b>>>();
    }

    // persistent fused GEMM: out = [A|x] @ Wt2 + bias
    cudaFuncSetAttribute(k_gemm_f16, cudaFuncAttributeMaxDynamicSharedMemorySize, SMEM_SZ);
    k_gemm_f16<<<GRID_P, 256, SMEM_SZ>>>(h_bias, out);
}

// round 16
// speedup vs baseline: 1.0851x; 1.0851x over previous
#include <cuda_runtime.h>
#include <cuda_fp16.h>
#include <cstdint>

#define N_NODES 50000
#define M_PAD   50048            // 391 * 128
#define N_EDGES 800000
#define FEAT    256
#define N_RELS  8
#define KA      2048             // A width (agg blocks only; x comes from g_xh)
#define KTOT    2304             // GEMM K = KA + FEAT
#define N_BUCK  (N_NODES * N_RELS)
#define SQRT_HALF 0.70710678118654752f

// ---------------- scratch ----------------------------------------------------
__device__ __half g_A[(size_t)M_PAD * KA];            // [aggx_0..7], fp16
__device__ __half g_xh[(size_t)M_PAD * FEAT];         // fp16 x
__device__ __half g_wt2[(size_t)FEAT * KTOT];         // [n][k] = W^T * sqrt(0.5)
__device__ int      g_counts[N_BUCK];
__device__ int      g_offsets[N_BUCK + 1];
__device__ int      g_cursor[N_BUCK];
__device__ int      g_blocksum[400];
__device__ int      g_blockpre[400];
__device__ unsigned g_sorted[N_EDGES];
__device__ unsigned g_tile_ctr;

#define SCAN_NB ((N_BUCK + 1023) / 1024)   // 391

// ---------------- sort pipeline: key = dst*8 + rel ---------------------------
__global__ void k_zero_counts() {
    int i = blockIdx.x * blockDim.x + threadIdx.x;
    if (i < N_BUCK) g_counts[i] = 0;
    if (i == 0) g_tile_ctr = 0;
}

__global__ void k_hist(const int* __restrict__ edge_index,
                       const int* __restrict__ edge_type) {
    int e = blockIdx.x * blockDim.x + threadIdx.x;
    if (e < N_EDGES) {
        int d = edge_index[N_EDGES + e];
        int r = edge_type[e];
        if (d >= 0 && d < N_NODES)
            atomicAdd(&g_counts[d * N_RELS + r], 1);
    }
}

__global__ void k_scan1() {
    __shared__ int s[1024];
    int idx = blockIdx.x * 1024 + threadIdx.x;
    int v = (idx < N_BUCK) ? g_counts[idx] : 0;
    s[threadIdx.x] = v;
    __syncthreads();
    for (int off = 512; off > 0; off >>= 1) {
        if (threadIdx.x < off) s[threadIdx.x] += s[threadIdx.x + off];
        __syncthreads();
    }
    if (threadIdx.x == 0) g_blocksum[blockIdx.x] = s[0];
}

__global__ void k_scan2() {
    __shared__ int s[512];
    int t = threadIdx.x;
    int v = (t < SCAN_NB) ? g_blocksum[t] : 0;
    s[t] = v;
    __syncthreads();
    int val = v;
    for (int off = 1; off < 512; off <<= 1) {
        int u = (t >= off) ? s[t - off] : 0;
        __syncthreads();
        val += u;
        s[t] = val;
        __syncthreads();
    }
    if (t < SCAN_NB) g_blockpre[t] = val - v;
    if (t == 0) g_offsets[N_BUCK] = N_EDGES;
}

__global__ void k_scan3() {
    __shared__ int s[1024];
    int idx = blockIdx.x * 1024 + threadIdx.x;
    int t = threadIdx.x;
    int v = (idx < N_BUCK) ? g_counts[idx] : 0;
    s[t] = v;
    __syncthreads();
    int val = v;
    for (int off = 1; off < 1024; off <<= 1) {
        int u = (t >= off) ? s[t - off] : 0;
        __syncthreads();
        val += u;
        s[t] = val;
        __syncthreads();
    }
    if (idx < N_BUCK) {
        int o = g_blockpre[blockIdx.x] + val - v;
        g_offsets[idx] = o;
        g_cursor[idx]  = o;
    }
}

__global__ void k_scatter(const int* __restrict__ edge_index,
                          const int* __restrict__ edge_type) {
    int e = blockIdx.x * blockDim.x + threadIdx.x;
    if (e < N_EDGES) {
        int srcv = edge_index[e];
        int d    = edge_index[N_EDGES + e];
        int r    = edge_type[e];
        if (d >= 0 && d < N_NODES) {
            int pos = atomicAdd(&g_cursor[d * N_RELS + r], 1);
            g_sorted[pos] = (unsigned)srcv;
        }
    }
}

// ---------------- converts ---------------------------------------------------
__global__ void k_convert_x(const float* __restrict__ x) {
    int i = blockIdx.x * blockDim.x + threadIdx.x;
    const int total = N_NODES * FEAT / 2;
    if (i < total) {
        float2 v = *((const float2*)x + i);
        *((__half2*)g_xh + i) = __floats2half2_rn(v.x, v.y);
    }
}

__global__ void k_convert_w(const float* __restrict__ W, const float* __restrict__ LW) {
    int r = blockIdx.z;
    const float* src = (r < N_RELS) ? (W + (size_t)r * FEAT * FEAT) : LW;
    int k0 = blockIdx.x * 32, n0 = blockIdx.y * 32;
    __shared__ float t[32][33];
    for (int i = threadIdx.y; i < 32; i += 8)
        t[i][threadIdx.x] = src[(size_t)(k0 + i) * FEAT + n0 + threadIdx.x];
    __syncthreads();
    for (int i = threadIdx.y; i < 32; i += 8)
        g_wt2[(size_t)(n0 + i) * KTOT + r * FEAT + k0 + threadIdx.x] =
            __float2half(t[threadIdx.x][i] * SQRT_HALF);
}

// ---------------- edge aggregation: 1 warp per (dst,rel) bucket --------------
// 2-stage software prefetch: next row load in flight while accumulating current.
__global__ __launch_bounds__(256) void k_agg_gather() {
    int p = blockIdx.x * 8 + threadIdx.y;
    if (p >= N_BUCK) return;
    int lane = threadIdx.x;
    int d = p >> 3, r = p & 7;
    int beg = g_offsets[p];
    int end = g_offsets[p + 1];

    float acc[8];
    #pragma unroll
    for (int j = 0; j < 8; j++) acc[j] = 0.f;

    if (beg < end) {
        unsigned s0 = g_sorted[beg];
        uint4 v = __ldg((const uint4*)(g_xh + ((size_t)s0 << 8)) + lane);
        for (int i = beg + 1; i < end; i++) {
            unsigned s1 = g_sorted[i];
            uint4 vn = __ldg((const uint4*)(g_xh + ((size_t)s1 << 8)) + lane);
            float2 f0 = __half22float2(*reinterpret_cast<const __half2*>(&v.x));
            float2 f1 = __half22float2(*reinterpret_cast<const __half2*>(&v.y));
            float2 f2 = __half22float2(*reinterpret_cast<const __half2*>(&v.z));
            float2 f3 = __half22float2(*reinterpret_cast<const __half2*>(&v.w));
            acc[0] += f0.x; acc[1] += f0.y; acc[2] += f1.x; acc[3] += f1.y;
            acc[4] += f2.x; acc[5] += f2.y; acc[6] += f3.x; acc[7] += f3.y;
            v = vn;
        }
        float2 f0 = __half22float2(*reinterpret_cast<const __half2*>(&v.x));
        float2 f1 = __half22float2(*reinterpret_cast<const __half2*>(&v.y));
        float2 f2 = __half22float2(*reinterpret_cast<const __half2*>(&v.z));
        float2 f3 = __half22float2(*reinterpret_cast<const __half2*>(&v.w));
        acc[0] += f0.x; acc[1] += f0.y; acc[2] += f1.x; acc[3] += f1.y;
        acc[4] += f2.x; acc[5] += f2.y; acc[6] += f3.x; acc[7] += f3.y;
    }

    __half2 h0 = __floats2half2_rn(acc[0], acc[1]);
    __half2 h1 = __floats2half2_rn(acc[2], acc[3]);
    __half2 h2 = __floats2half2_rn(acc[4], acc[5]);
    __half2 h3 = __floats2half2_rn(acc[6], acc[7]);
    uint4 o;
    o.x = *reinterpret_cast<unsigned*>(&h0);
    o.y = *reinterpret_cast<unsigned*>(&h1);
    o.z = *reinterpret_cast<unsigned*>(&h2);
    o.w = *reinterpret_cast<unsigned*>(&h3);
    *(uint4*)(g_A + (size_t)d * KA + r * FEAT + lane * 8) = o;
}

// ---------------- fp16 mma GEMM: out = [A|x] @ Wt2^T + bias ------------------
// EXACT round-13 structure: persistent 128x128 tiles, 3-stage cp.async,
// load-issued-BEFORE-wait, two syncs per iteration, 2 CTAs/SM.
#define GBM 128
#define GBN 128
#define GBK 32
#define PITCH 40                       // halfs per smem row (80 B)
#define ASTAGE (GBM * PITCH)           // 5120 halfs
#define BSTAGE (GBN * PITCH)           // 5120 halfs
#define OFF_B  (3 * ASTAGE)
#define SMEM_SZ ((3 * ASTAGE + 3 * BSTAGE) * 2)   // 61440 B
#define NTILES ((M_PAD / GBM) * (FEAT / GBN))     // 782
#define GRID_P 296                                 // 148 SMs x 2 CTAs

__device__ __forceinline__ void cp16(void* dst, const void* src) {
    unsigned s = (unsigned)__cvta_generic_to_shared(dst);
    asm volatile("cp.async.cg.shared.global [%0],[%1],16;" :: "r"(s), "l"(src));
}
__device__ __forceinline__ void cp_commit() { asm volatile("cp.async.commit_group;"); }
template<int N> __device__ __forceinline__ void cp_wait() {
    asm volatile("cp.async.wait_group %0;" :: "n"(N));
}
__device__ __forceinline__ void ldm_x4(unsigned r[4], const void* p) {
    unsigned a = (unsigned)__cvta_generic_to_shared(p);
    asm volatile("ldmatrix.sync.aligned.m8n8.x4.shared.b16 {%0,%1,%2,%3},[%4];"
                 : "=r"(r[0]), "=r"(r[1]), "=r"(r[2]), "=r"(r[3]) : "r"(a));
}
__device__ __forceinline__ void mma_f16(float c[4], const unsigned a[4], const unsigned b[2]) {
    asm volatile(
        "mma.sync.aligned.m16n8k16.row.col.f32.f16.f16.f32 "
        "{%0,%1,%2,%3},{%4,%5,%6,%7},{%8,%9},{%0,%1,%2,%3};"
        : "+f"(c[0]), "+f"(c[1]), "+f"(c[2]), "+f"(c[3])
        : "r"(a[0]), "r"(a[1]), "r"(a[2]), "r"(a[3]), "r"(b[0]), "r"(b[1]));
}

__global__ __launch_bounds__(256, 2) void k_gemm_f16(
    const float* __restrict__ h_bias, float* __restrict__ out)
{
    extern __shared__ __half smem[];
    __half* As = smem;            // 3 stages of GBM x GBK
    __half* Bs = smem + OFF_B;    // 3 stages of GBN x GBK
    __shared__ unsigned s_tile;

    const int tid  = threadIdx.x;
    const int lane = tid & 31;
    const int warp = tid >> 5;    // 0..7
    const int wm   = warp & 3;    // 4 warps in m: 32 rows each
    const int wn   = warp >> 2;   // 2 warps in n: 64 cols each

    for (;;) {
        if (tid == 0) s_tile = atomicAdd(&g_tile_ctr, 1u);
        __syncthreads();
        unsigned tile = s_tile;
        if (tile >= NTILES) break;

        const int n0 = (int)(tile & 1) * GBN;     // n halves adjacent -> L2 A share
        const int m0 = (int)(tile >> 1) * GBM;

        float c[2][8][4];
        #pragma unroll
        for (int i = 0; i < 2; i++)
            #pragma unroll
            for (int j = 0; j < 8; j++)
                #pragma unroll
                for (int q = 0; q < 4; q++) c[i][j][q] = 0.f;

        auto load_stage = [&](int st, int k0) {
            #pragma unroll
            for (int j = 0; j < 2; j++) {
                int idx = tid + j * 256;
                int row = idx >> 2, seg = idx & 3;   // 128 rows x 4 segs
                const __half* srcA = (k0 < KA)
                    ? g_A  + (size_t)(m0 + row) * KA   + k0          + seg * 8
                    : g_xh + (size_t)(m0 + row) * FEAT + (k0 - KA)  + seg * 8;
                cp16(&As[st * ASTAGE + row * PITCH + seg * 8], srcA);
                cp16(&Bs[st * BSTAGE + row * PITCH + seg * 8],
                     g_wt2 + (size_t)(n0 + row) * KTOT + k0 + seg * 8);
            }
        };

        load_stage(0, 0);   cp_commit();
        load_stage(1, GBK); cp_commit();

        const int NSTAGES = KTOT / GBK;  // 72
        for (int it = 0; it < NSTAGES; it++) {
            int buf = it % 3;
            if (it + 2 < NSTAGES) {
                load_stage((it + 2) % 3, (it + 2) * GBK);
                cp_commit();
                cp_wait<2>();
            } else if (it + 1 < NSTAGES) {
                cp_wait<1>();
            } else {
                cp_wait<0>();
            }
            __syncthreads();

            const __half* Ab = &As[buf * ASTAGE];
            const __half* Bb = &Bs[buf * BSTAGE];
            #pragma unroll
            for (int ks = 0; ks < 2; ks++) {
                const int kb = ks * 16;
                unsigned a[2][4];
                #pragma unroll
                for (int mf = 0; mf < 2; mf++) {
                    int mrow = wm * 32 + mf * 16 + (lane & 15);
                    ldm_x4(a[mf], Ab + mrow * PITCH + kb + ((lane >> 4) << 3));
                }
                unsigned b[8][2];
                #pragma unroll
                for (int nb = 0; nb < 4; nb++) {
                    int nrow = wn * 64 + nb * 16 + (lane & 7) + ((lane >> 4) << 3);
                    unsigned t[4];
                    ldm_x4(t, Bb + nrow * PITCH + kb + (((lane >> 3) & 1) << 3));
                    b[2 * nb][0] = t[0]; b[2 * nb][1] = t[1];
                    b[2 * nb + 1][0] = t[2]; b[2 * nb + 1][1] = t[3];
                }
                #pragma unroll
                for (int mf = 0; mf < 2; mf++)
                    #pragma unroll
                    for (int nf = 0; nf < 8; nf++)
                        mma_f16(c[mf][nf], a[mf], b[nf]);
            }
            __syncthreads();
        }

        // epilogue: out = C + bias
        #pragma unroll
        for (int mf = 0; mf < 2; mf++) {
            int row0 = m0 + wm * 32 + mf * 16 + (lane >> 2);
            #pragma unroll
            for (int nf = 0; nf < 8; nf++) {
                int col = n0 + wn * 64 + nf * 8 + (lane & 3) * 2;
                float2 bv = *(const float2*)(h_bias + col);
                if (row0 < N_NODES)
                    *(float2*)(out + ((size_t)row0 << 8) + col) =
                        make_float2(bv.x + c[mf][nf][0], bv.y + c[mf][nf][1]);
                if (row0 + 8 < N_NODES)
                    *(float2*)(out + ((size_t)(row0 + 8) << 8) + col) =
                        make_float2(bv.x + c[mf][nf][2], bv.y + c[mf][nf][3]);
            }
        }
    }
}

// ---------------- launch -----------------------------------------------------
extern "C" void kernel_launch(void* const* d_in, const int* in_sizes, int n_in,
                              void* d_out, int out_size) {
    const int*   edge_index  = (const int*)d_in[0];
    const float* x           = (const float*)d_in[1];
    const int*   edge_type   = (const int*)d_in[2];
    const float* weight      = (const float*)d_in[3];
    const float* h_bias      = (const float*)d_in[4];
    const float* loop_weight = (const float*)d_in[5];
    float* out = (float*)d_out;

    // converts
    k_convert_x<<<(N_NODES * FEAT / 2 + 255) / 256, 256>>>(x);
    {
        dim3 b(32, 8), g(FEAT / 32, FEAT / 32, N_RELS + 1);
        k_convert_w<<<g, b>>>(weight, loop_weight);
    }

    // sort pipeline over (dst, rel) buckets
    k_zero_counts<<<(N_BUCK + 255) / 256, 256>>>();
    k_hist<<<(N_EDGES + 255) / 256, 256>>>(edge_index, edge_type);
    k_scan1<<<SCAN_NB, 1024>>>();
    k_scan2<<<1, 512>>>();
    k_scan3<<<SCAN_NB, 1024>>>();
    k_scatter<<<(N_EDGES + 255) / 256, 256>>>(edge_index, edge_type);

    // edge aggregation into A
    {
        dim3 b(32, 8);
        k_agg_gather<<<(N_BUCK + 7) / 8, b>>>();
    }

    // persistent fused GEMM: out = [A|x] @ Wt2 + bias
    cudaFuncSetAttribute(k_gemm_f16, cudaFuncAttributeMaxDynamicSharedMemorySize, SMEM_SZ);
    k_gemm_f16<<<GRID_P, 256, SMEM_SZ>>>(h_bias, out);
}